// round 1
// baseline (speedup 1.0000x reference)
#include <cuda_runtime.h>
#include <math.h>

#define Nn 8
#define Cc 14
#define Hh 512
#define Ww 512
#define HW (Hh*Ww)
#define PIX (Nn*HW)
#define ROWS (Nn*Cc)   // 112
#define PARTS 8

// ---- scratch (device globals; no allocation allowed) ----
__device__ unsigned char  g_tmap[PIX];
__device__ unsigned short g_mag[PIX];
__device__ unsigned char  g_sect[PIX];
__device__ unsigned char  g_strong[PIX];
__device__ unsigned char  g_weak[PIX];
__device__ unsigned char  g_hyst[PIX];
__device__ unsigned char  g_dh[PIX];
__device__ unsigned char  g_dv[PIX];
__device__ unsigned short g_bh[PIX];
__device__ float          g_e[PIX];
__device__ float          g_part[ROWS*PARTS*5];

// ---------------- 1. teacher argmax -> uint8 gray map ----------------
__global__ void k_argmax(const float* __restrict__ T) {
    int p = blockIdx.x * blockDim.x + threadIdx.x;
    if (p >= PIX) return;
    int n = p / HW, sp = p % HW;
    const float* base = T + (size_t)n * Cc * HW + sp;
    float best = base[0];
    int bi = 0;
#pragma unroll
    for (int c = 1; c < Cc; c++) {
        float v = base[(size_t)c * HW];
        if (v > best) { best = v; bi = c; }   // strict > : first occurrence wins
    }
    float fv = (float)bi / 13.0f * 255.0f;    // match jax f32 op order
    g_tmap[p] = (unsigned char)fv;            // truncating cast
}

// ---------------- 2a. Sobel (replicate pad) -> L1 mag + sector ----------------
__global__ void k_sobel() {
    int p = blockIdx.x * blockDim.x + threadIdx.x;
    if (p >= PIX) return;
    int n = p / HW, sp = p % HW;
    int y = sp / Ww, x = sp % Ww;
    int ym = y > 0 ? y - 1 : 0, yp = y < Hh - 1 ? y + 1 : Hh - 1;
    int xm = x > 0 ? x - 1 : 0, xp = x < Ww - 1 ? x + 1 : Ww - 1;
    const unsigned char* b = g_tmap + n * HW;
    int a0 = b[ym * Ww + xm], a1 = b[ym * Ww + x], a2 = b[ym * Ww + xp];
    int a3 = b[y  * Ww + xm],                       a5 = b[y  * Ww + xp];
    int a6 = b[yp * Ww + xm], a7 = b[yp * Ww + x], a8 = b[yp * Ww + xp];
    int gx = (a2 + 2 * a5 + a8) - (a0 + 2 * a3 + a6);
    int gy = (a6 + 2 * a7 + a8) - (a0 + 2 * a1 + a2);
    int mag = abs(gx) + abs(gy);
    g_mag[p] = (unsigned short)mag;
    float ang = atan2f((float)gy, (float)gx) * 57.29577951308232f;
    if (ang < 0.0f)    ang += 180.0f;
    if (ang >= 180.0f) ang -= 180.0f;
    unsigned char s;
    if (ang < 22.5f || ang >= 157.5f) s = 0;
    else if (ang < 67.5f)             s = 1;
    else if (ang < 112.5f)            s = 2;
    else                              s = 3;
    g_sect[p] = s;
}

// ---------------- 2b. NMS + hysteresis thresholds ----------------
__global__ void k_nms() {
    int p = blockIdx.x * blockDim.x + threadIdx.x;
    if (p >= PIX) return;
    int n = p / HW, sp = p % HW;
    int y = sp / Ww, x = sp % Ww;
    int m = g_mag[p];
    unsigned char s = g_sect[p];
    int dy1, dx1, dy2, dx2;
    if (s == 0)      { dy1 = 0;  dx1 = 1;  dy2 = 0; dx2 = -1; }
    else if (s == 1) { dy1 = -1; dx1 = 1;  dy2 = 1; dx2 = -1; }
    else if (s == 2) { dy1 = -1; dx1 = 0;  dy2 = 1; dx2 = 0;  }
    else             { dy1 = -1; dx1 = -1; dy2 = 1; dx2 = 1;  }
    int y1 = y + dy1, x1 = x + dx1, y2 = y + dy2, x2 = x + dx2;
    int n1 = (y1 < 0 || y1 >= Hh || x1 < 0 || x1 >= Ww) ? 0 : g_mag[n * HW + y1 * Ww + x1];
    int n2 = (y2 < 0 || y2 >= Hh || x2 < 0 || x2 >= Ww) ? 0 : g_mag[n * HW + y2 * Ww + x2];
    int nms = (m >= n1 && m >= n2) ? m : 0;
    g_strong[p] = nms > 50 ? 1 : 0;
    g_weak[p]   = nms > 10 ? 1 : 0;
}

// ---------------- 3. 16-iter hysteresis, one launch, SMEM tiles ----------------
#define TILE 64
#define HALO 16
#define SS 96
__global__ void k_hyst() {
    __shared__ unsigned char wk[SS * SS], bufA[SS * SS], bufB[SS * SS];
    const int tpr = Ww / TILE;               // 8
    const int tpi = (Hh / TILE) * tpr;       // 64
    int img = blockIdx.x / tpi;
    int t = blockIdx.x % tpi;
    int oy = (t / tpr) * TILE - HALO;
    int ox = (t % tpr) * TILE - HALO;
    for (int i = threadIdx.x; i < SS * SS; i += blockDim.x) {
        int ly = i / SS, lx = i % SS;
        int gy = oy + ly, gx = ox + lx;
        bool in = (gy >= 0 && gy < Hh && gx >= 0 && gx < Ww);
        int gp = img * HW + gy * Ww + gx;
        wk[i]   = in ? g_weak[gp]   : 0;
        bufA[i] = in ? g_strong[gp] : 0;
    }
    __syncthreads();
    unsigned char* cur = bufA;
    unsigned char* nxt = bufB;
    for (int k = 1; k <= 16; k++) {
        int lo = k, hi = SS - k;           // valid region shrinks; center stays exact
        for (int i = threadIdx.x; i < SS * SS; i += blockDim.x) {
            int ly = i / SS, lx = i % SS;
            if (ly >= lo && ly < hi && lx >= lo && lx < hi) {
                int o = cur[i - SS - 1] | cur[i - SS] | cur[i - SS + 1]
                      | cur[i - 1]      | cur[i]      | cur[i + 1]
                      | cur[i + SS - 1] | cur[i + SS] | cur[i + SS + 1];
                nxt[i] = (o && wk[i]) ? 1 : 0;
            }
        }
        __syncthreads();
        unsigned char* tmp = cur; cur = nxt; nxt = tmp;
    }
    for (int i = threadIdx.x; i < TILE * TILE; i += blockDim.x) {
        int ly = i / TILE + HALO, lx = i % TILE + HALO;
        g_hyst[img * HW + (oy + ly) * Ww + (ox + lx)] = cur[ly * SS + lx];
    }
}

// ---------------- 4. dilate 10x10, separable, pad (5,4) ----------------
__global__ void k_dil_h() {
    int p = blockIdx.x * blockDim.x + threadIdx.x;
    if (p >= PIX) return;
    int n = p / HW, sp = p % HW;
    int y = sp / Ww, x = sp % Ww;
    int lo = x - 5 > 0 ? x - 5 : 0;
    int hi = x + 4 < Ww - 1 ? x + 4 : Ww - 1;
    const unsigned char* b = g_hyst + n * HW + y * Ww;
    unsigned char v = 0;
    for (int j = lo; j <= hi; j++) v |= b[j];
    g_dh[p] = v;
}
__global__ void k_dil_v() {
    int p = blockIdx.x * blockDim.x + threadIdx.x;
    if (p >= PIX) return;
    int n = p / HW, sp = p % HW;
    int y = sp / Ww, x = sp % Ww;
    int lo = y - 5 > 0 ? y - 5 : 0;
    int hi = y + 4 < Hh - 1 ? y + 4 : Hh - 1;
    const unsigned char* b = g_dh + n * HW;
    unsigned char v = 0;
    for (int j = lo; j <= hi; j++) v |= b[j * Ww + x];
    g_dv[p] = v;
}

// ---------------- 5. box blur 10x10, separable, reflect101, round, /255 ----------------
__global__ void k_blur_h() {
    int p = blockIdx.x * blockDim.x + threadIdx.x;
    if (p >= PIX) return;
    int n = p / HW, sp = p % HW;
    int y = sp / Ww, x = sp % Ww;
    const unsigned char* b = g_dv + n * HW + y * Ww;
    int s = 0;
#pragma unroll
    for (int dx = -5; dx <= 4; dx++) {
        int xx = x + dx;
        if (xx < 0) xx = -xx;
        else if (xx >= Ww) xx = 2 * Ww - 2 - xx;
        s += b[xx];
    }
    g_bh[p] = (unsigned short)s;
}
__global__ void k_blur_v() {
    int p = blockIdx.x * blockDim.x + threadIdx.x;
    if (p >= PIX) return;
    int n = p / HW, sp = p % HW;
    int y = sp / Ww, x = sp % Ww;
    const unsigned short* b = g_bh + n * HW;
    int s = 0;
#pragma unroll
    for (int dy = -5; dy <= 4; dy++) {
        int yy = y + dy;
        if (yy < 0) yy = -yy;
        else if (yy >= Hh) yy = 2 * Hh - 2 - yy;
        s += b[yy * Ww + x];
    }
    float bb = (float)(s * 255) / 100.0f;   // exact integer sum, f32 divide (matches ref)
    g_e[p] = rintf(bb) / 255.0f;            // round half-to-even == jnp.round
}

// ---------------- 6. fused masked channel-softmax KL (online, single read) ----------------
__global__ void k_kd(const float* __restrict__ S, const float* __restrict__ T) {
    int r = blockIdx.x;                 // 0..111 : (n,c)
    int part = blockIdx.y;              // 0..PARTS-1
    int n = r / Cc, c = r % Cc;
    const float4* e4 = (const float4*)(g_e + (size_t)n * HW);
    const float4* t4 = (const float4*)(T + ((size_t)n * Cc + c) * HW);
    const float4* s4 = (const float4*)(S + ((size_t)n * Cc + c) * HW);
    const int q4 = HW / 4 / PARTS;      // 8192 float4 per partial
    const int base = part * q4;

    float mt = -INFINITY, zt = 0.f, st = 0.f;
    float ms = -INFINITY, zs = 0.f;

    for (int k = threadIdx.x; k < q4; k += blockDim.x) {
        float4 ev = e4[base + k];
        float4 tv = t4[base + k];
        float4 sv = s4[base + k];
        float el[4] = {ev.x, ev.y, ev.z, ev.w};
        float tl[4] = {tv.x, tv.y, tv.z, tv.w};
        float sl[4] = {sv.x, sv.y, sv.z, sv.w};
#pragma unroll
        for (int j = 0; j < 4; j++) {
            float xt = el[j] * tl[j];
            float xs = el[j] * sl[j];
            if (xt > mt) { float sc = expf(mt - xt); zt *= sc; st *= sc; mt = xt; }
            float w = expf(xt - mt);
            zt += w;
            st += w * (xt - xs);
            if (xs > ms) { zs *= expf(ms - xs); ms = xs; }
            zs += expf(xs - ms);
        }
    }

    __shared__ float r0[256], r1[256], r2[256], r3[256], r4[256];
    int tid = threadIdx.x;
    r0[tid] = mt; r1[tid] = zt; r2[tid] = st; r3[tid] = ms; r4[tid] = zs;
    __syncthreads();
    for (int off = 128; off > 0; off >>= 1) {
        if (tid < off) {
            float m2 = r0[tid + off], z2 = r1[tid + off], s2 = r2[tid + off];
            float nm = fmaxf(r0[tid], m2);
            float e1 = expf(r0[tid] - nm), e2 = expf(m2 - nm);
            r1[tid] = r1[tid] * e1 + z2 * e2;
            r2[tid] = r2[tid] * e1 + s2 * e2;
            r0[tid] = nm;
            float m2b = r3[tid + off], z2b = r4[tid + off];
            float nmb = fmaxf(r3[tid], m2b);
            r4[tid] = r4[tid] * expf(r3[tid] - nmb) + z2b * expf(m2b - nmb);
            r3[tid] = nmb;
        }
        __syncthreads();
    }
    if (tid == 0) {
        float* q = &g_part[(r * PARTS + part) * 5];
        q[0] = r0[0]; q[1] = r1[0]; q[2] = r2[0]; q[3] = r3[0]; q[4] = r4[0];
    }
}

__global__ void k_final(float* __restrict__ out) {
    __shared__ float acc[128];
    int r = threadIdx.x;
    float term = 0.0f;
    if (r < ROWS) {
        float mt = -INFINITY, zt = 0.f, st = 0.f, ms = -INFINITY, zs = 0.f;
        for (int p = 0; p < PARTS; p++) {
            const float* q = &g_part[(r * PARTS + p) * 5];
            float m2 = q[0], z2 = q[1], s2 = q[2];
            float nm = fmaxf(mt, m2);
            float e1 = expf(mt - nm), e2 = expf(m2 - nm);
            zt = zt * e1 + z2 * e2;
            st = st * e1 + s2 * e2;
            mt = nm;
            float m2b = q[3], z2b = q[4];
            float nmb = fmaxf(ms, m2b);
            zs = zs * expf(ms - nmb) + z2b * expf(m2b - nmb);
            ms = nmb;
        }
        // row KL = E_pt[xt-xs] - lse_t + lse_s
        term = st / zt - (mt + logf(zt)) + (ms + logf(zs));
    }
    acc[threadIdx.x] = term;
    __syncthreads();
    for (int off = 64; off > 0; off >>= 1) {
        if (threadIdx.x < off) acc[threadIdx.x] += acc[threadIdx.x + off];
        __syncthreads();
    }
    if (threadIdx.x == 0) out[0] = acc[0] / 112.0f;   // /(n*c), T^2 = 1
}

// ---------------- launch ----------------
extern "C" void kernel_launch(void* const* d_in, const int* in_sizes, int n_in,
                              void* d_out, int out_size) {
    const float* S = (const float*)d_in[0];
    const float* T = (const float*)d_in[1];
    float* out = (float*)d_out;
    const int thr = 256;
    const int blks = (PIX + thr - 1) / thr;

    k_argmax<<<blks, thr>>>(T);
    k_sobel<<<blks, thr>>>();
    k_nms<<<blks, thr>>>();
    k_hyst<<<Nn * 64, 256>>>();
    k_dil_h<<<blks, thr>>>();
    k_dil_v<<<blks, thr>>>();
    k_blur_h<<<blks, thr>>>();
    k_blur_v<<<blks, thr>>>();
    dim3 g(ROWS, PARTS);
    k_kd<<<g, 256>>>(S, T);
    k_final<<<1, 128>>>(out);
}

// round 2
// speedup vs baseline: 1.9768x; 1.9768x over previous
#include <cuda_runtime.h>
#include <math.h>

#define Nn 8
#define Cc 14
#define Hh 512
#define Ww 512
#define HW (Hh*Ww)
#define PIX (Nn*HW)
#define ROWS (Nn*Cc)   // 112
#define PARTS 8
#define WPR 16         // 512-bit row = 16 u32 words

// ---- scratch (device globals; no allocation allowed) ----
__device__ unsigned char  g_tmap[PIX];
__device__ unsigned short g_mag[PIX];
__device__ unsigned char  g_sect[PIX];
__device__ unsigned int   g_strongb[PIX/32];
__device__ unsigned int   g_weakb[PIX/32];
__device__ unsigned int   g_dvb[PIX/32];
__device__ unsigned short g_bh[PIX];
__device__ float          g_e[PIX];
__device__ float          g_part[ROWS*PARTS*5];

// ---------------- 1. teacher argmax -> uint8 gray map (float4 vectorized) ----------------
__global__ void k_argmax(const float* __restrict__ T) {
    int p4 = blockIdx.x * blockDim.x + threadIdx.x;
    if (p4 >= PIX / 4) return;
    int n = p4 / (HW / 4), sp4 = p4 % (HW / 4);
    const float4* base = (const float4*)(T + (size_t)n * Cc * HW) + sp4;
    float4 best = base[0];
    int i0 = 0, i1 = 0, i2 = 0, i3 = 0;
#pragma unroll
    for (int c = 1; c < Cc; c++) {
        float4 v = base[(size_t)c * (HW / 4)];
        if (v.x > best.x) { best.x = v.x; i0 = c; }
        if (v.y > best.y) { best.y = v.y; i1 = c; }
        if (v.z > best.z) { best.z = v.z; i2 = c; }
        if (v.w > best.w) { best.w = v.w; i3 = c; }
    }
    unsigned char b0 = (unsigned char)((float)i0 / 13.0f * 255.0f);
    unsigned char b1 = (unsigned char)((float)i1 / 13.0f * 255.0f);
    unsigned char b2 = (unsigned char)((float)i2 / 13.0f * 255.0f);
    unsigned char b3 = (unsigned char)((float)i3 / 13.0f * 255.0f);
    ((unsigned int*)g_tmap)[p4] =
        (unsigned)b0 | ((unsigned)b1 << 8) | ((unsigned)b2 << 16) | ((unsigned)b3 << 24);
}

// ---------------- 2a. Sobel (replicate pad) -> L1 mag + sector ----------------
__global__ void k_sobel() {
    int p = blockIdx.x * blockDim.x + threadIdx.x;
    if (p >= PIX) return;
    int n = p / HW, sp = p % HW;
    int y = sp / Ww, x = sp % Ww;
    int ym = y > 0 ? y - 1 : 0, yp = y < Hh - 1 ? y + 1 : Hh - 1;
    int xm = x > 0 ? x - 1 : 0, xp = x < Ww - 1 ? x + 1 : Ww - 1;
    const unsigned char* b = g_tmap + n * HW;
    int a0 = b[ym * Ww + xm], a1 = b[ym * Ww + x], a2 = b[ym * Ww + xp];
    int a3 = b[y  * Ww + xm],                       a5 = b[y  * Ww + xp];
    int a6 = b[yp * Ww + xm], a7 = b[yp * Ww + x], a8 = b[yp * Ww + xp];
    int gx = (a2 + 2 * a5 + a8) - (a0 + 2 * a3 + a6);
    int gy = (a6 + 2 * a7 + a8) - (a0 + 2 * a1 + a2);
    int mag = abs(gx) + abs(gy);
    g_mag[p] = (unsigned short)mag;
    float ang = atan2f((float)gy, (float)gx) * 57.29577951308232f;
    if (ang < 0.0f)    ang += 180.0f;
    if (ang >= 180.0f) ang -= 180.0f;
    unsigned char s;
    if (ang < 22.5f || ang >= 157.5f) s = 0;
    else if (ang < 67.5f)             s = 1;
    else if (ang < 112.5f)            s = 2;
    else                              s = 3;
    g_sect[p] = s;
}

// ---------------- 2b. NMS + thresholds -> bit-packed strong/weak ----------------
__global__ void k_nms() {
    int p = blockIdx.x * blockDim.x + threadIdx.x;   // grid sized exactly PIX
    int n = p / HW, sp = p % HW;
    int y = sp / Ww, x = sp % Ww;
    int m = g_mag[p];
    unsigned char s = g_sect[p];
    int dy1, dx1, dy2, dx2;
    if (s == 0)      { dy1 = 0;  dx1 = 1;  dy2 = 0; dx2 = -1; }
    else if (s == 1) { dy1 = -1; dx1 = 1;  dy2 = 1; dx2 = -1; }
    else if (s == 2) { dy1 = -1; dx1 = 0;  dy2 = 1; dx2 = 0;  }
    else             { dy1 = -1; dx1 = -1; dy2 = 1; dx2 = 1;  }
    int y1 = y + dy1, x1 = x + dx1, y2 = y + dy2, x2 = x + dx2;
    int n1 = (y1 < 0 || y1 >= Hh || x1 < 0 || x1 >= Ww) ? 0 : g_mag[n * HW + y1 * Ww + x1];
    int n2 = (y2 < 0 || y2 >= Hh || x2 < 0 || x2 >= Ww) ? 0 : g_mag[n * HW + y2 * Ww + x2];
    int nms = (m >= n1 && m >= n2) ? m : 0;
    unsigned sm = __ballot_sync(0xffffffffu, nms > 50);
    unsigned wm = __ballot_sync(0xffffffffu, nms > 10);
    if ((threadIdx.x & 31) == 0) {
        g_strongb[p >> 5] = sm;
        g_weakb[p >> 5]   = wm;
    }
}

// ---------------- 3. bitboard hysteresis (16 iters) + fused 10x10 dilate ----------------
#define CORE 32
#define HAL  24            // 16 iters + 5 dilate + margin
#define SH   (CORE + 2*HAL)  // 80 rows
#define SW   (SH * WPR)      // 1280 words

__global__ void k_hyst_dil() {
    __shared__ unsigned wk[SW], cur[SW], Hb[SW];
    int img   = blockIdx.x >> 4;
    int strip = blockIdx.x & 15;
    int gy0 = strip * CORE - HAL;
    for (int i = threadIdx.x; i < SW; i += blockDim.x) {
        int row = i >> 4, wi = i & 15;
        int gy = gy0 + row;
        bool in = (gy >= 0 && gy < Hh);
        int gw = (img * Hh + gy) * WPR + wi;
        wk[i]  = in ? g_weakb[gw]   : 0u;
        cur[i] = in ? g_strongb[gw] : 0u;
    }
    __syncthreads();
    for (int it = 0; it < 16; it++) {
        // horizontal 3-dilate
        for (int i = threadIdx.x; i < SW; i += blockDim.x) {
            int wi = i & 15;
            unsigned c = cur[i];
            unsigned l = wi        ? cur[i - 1] : 0u;
            unsigned r = (wi < 15) ? cur[i + 1] : 0u;
            Hb[i] = c | (c << 1) | (l >> 31) | (c >> 1) | (r << 31);
        }
        __syncthreads();
        // vertical 3-dilate & weak mask
        for (int i = threadIdx.x; i < SW; i += blockDim.x) {
            unsigned u = (i >= WPR)      ? Hb[i - WPR] : 0u;
            unsigned d = (i < SW - WPR)  ? Hb[i + WPR] : 0u;
            cur[i] = wk[i] & (Hb[i] | u | d);
        }
        __syncthreads();
    }
    // horizontal dilate, window [x-5, x+4]
    for (int i = threadIdx.x; i < SW; i += blockDim.x) {
        int wi = i & 15;
        unsigned c = cur[i];
        unsigned l = wi        ? cur[i - 1] : 0u;
        unsigned r = (wi < 15) ? cur[i + 1] : 0u;
        unsigned long long lo = (unsigned long long)l | ((unsigned long long)c << 32);
        unsigned long long hi = (unsigned long long)c | ((unsigned long long)r << 32);
        unsigned o = 0;
#pragma unroll
        for (int d2 = 0; d2 <= 4; d2++) o |= (unsigned)(hi >> d2);
#pragma unroll
        for (int d2 = 1; d2 <= 5; d2++) o |= (unsigned)(lo >> (32 - d2));
        Hb[i] = o;
    }
    __syncthreads();
    // vertical dilate, window [y-5, y+4]; core rows only
    for (int i = threadIdx.x; i < CORE * WPR; i += blockDim.x) {
        int row = (i >> 4) + HAL, wi = i & 15;
        unsigned o = 0;
#pragma unroll
        for (int dy2 = -5; dy2 <= 4; dy2++) o |= Hb[(row + dy2) * WPR + wi];
        int gy = gy0 + row;
        g_dvb[(img * Hh + gy) * WPR + wi] = o;
    }
}

// ---------------- 4. blur_h on bitboard: popcount 10-bit windows, reflect101 ----------------
__global__ void k_blur_h() {
    int idx = blockIdx.x * blockDim.x + threadIdx.x;  // word index
    if (idx >= PIX / 32) return;
    int wi = idx & 15;
    unsigned wc = g_dvb[idx];
    unsigned wl = wi        ? g_dvb[idx - 1] : 0u;
    unsigned wr = (wi < 15) ? g_dvb[idx + 1] : 0u;
    unsigned long long lo = (unsigned long long)wl | ((unsigned long long)wc << 32);
    unsigned long long hi = (unsigned long long)wc | ((unsigned long long)wr << 32);
    unsigned short vals[32];
#pragma unroll
    for (int b = 0; b < 32; b++) {
        int x = wi * 32 + b;
        int s;
        if (x >= 5 && x < Ww - 4) {
            unsigned long long win = (b <= 27) ? (lo >> (b + 27)) : (hi >> (b - 5));
            s = __popcll(win & 0x3FFull);
        } else {
            s = 0;
            for (int dx = -5; dx <= 4; dx++) {
                int xx = x + dx;
                if (xx < 0) xx = -xx;
                else if (xx >= Ww) xx = 2 * Ww - 2 - xx;
                s += (wc >> (xx - wi * 32)) & 1;   // reflected taps stay within wc
            }
        }
        vals[b] = (unsigned short)s;
    }
    uint4* dst = (uint4*)(g_bh + (size_t)idx * 32);
    uint4* src = (uint4*)vals;
#pragma unroll
    for (int q = 0; q < 4; q++) dst[q] = src[q];
}

// ---------------- 5. blur_v, reflect101, round-half-even, /255 ----------------
__global__ void k_blur_v() {
    int p = blockIdx.x * blockDim.x + threadIdx.x;
    if (p >= PIX) return;
    int n = p / HW, sp = p % HW;
    int y = sp / Ww, x = sp % Ww;
    const unsigned short* b = g_bh + n * HW;
    int s = 0;
#pragma unroll
    for (int dy = -5; dy <= 4; dy++) {
        int yy = y + dy;
        if (yy < 0) yy = -yy;
        else if (yy >= Hh) yy = 2 * Hh - 2 - yy;
        s += b[yy * Ww + x];
    }
    float bb = (float)(s * 255) / 100.0f;
    g_e[p] = rintf(bb) / 255.0f;
}

// ---------------- 6. fused masked channel-softmax KL (online, single read) ----------------
__global__ void k_kd(const float* __restrict__ S, const float* __restrict__ T) {
    int r = blockIdx.x;                 // 0..111 : (n,c)
    int part = blockIdx.y;              // 0..PARTS-1
    int n = r / Cc, c = r % Cc;
    const float4* e4 = (const float4*)(g_e + (size_t)n * HW);
    const float4* t4 = (const float4*)(T + ((size_t)n * Cc + c) * HW);
    const float4* s4 = (const float4*)(S + ((size_t)n * Cc + c) * HW);
    const int q4 = HW / 4 / PARTS;      // 8192 float4 per partial
    const int base = part * q4;

    float mt = -INFINITY, zt = 0.f, st = 0.f;
    float ms = -INFINITY, zs = 0.f;

    for (int k = threadIdx.x; k < q4; k += blockDim.x) {
        float4 ev = e4[base + k];
        float4 tv = t4[base + k];
        float4 sv = s4[base + k];
        float el[4] = {ev.x, ev.y, ev.z, ev.w};
        float tl[4] = {tv.x, tv.y, tv.z, tv.w};
        float sl[4] = {sv.x, sv.y, sv.z, sv.w};
#pragma unroll
        for (int j = 0; j < 4; j++) {
            float xt = el[j] * tl[j];
            float xs = el[j] * sl[j];
            if (xt > mt) { float sc = expf(mt - xt); zt *= sc; st *= sc; mt = xt; }
            float w = expf(xt - mt);
            zt += w;
            st += w * (xt - xs);
            if (xs > ms) { zs *= expf(ms - xs); ms = xs; }
            zs += expf(xs - ms);
        }
    }

    __shared__ float r0[256], r1[256], r2[256], r3[256], r4[256];
    int tid = threadIdx.x;
    r0[tid] = mt; r1[tid] = zt; r2[tid] = st; r3[tid] = ms; r4[tid] = zs;
    __syncthreads();
    for (int off = 128; off > 0; off >>= 1) {
        if (tid < off) {
            float m2 = r0[tid + off], z2 = r1[tid + off], s2 = r2[tid + off];
            float nm = fmaxf(r0[tid], m2);
            float e1 = expf(r0[tid] - nm), e2 = expf(m2 - nm);
            r1[tid] = r1[tid] * e1 + z2 * e2;
            r2[tid] = r2[tid] * e1 + s2 * e2;
            r0[tid] = nm;
            float m2b = r3[tid + off], z2b = r4[tid + off];
            float nmb = fmaxf(r3[tid], m2b);
            r4[tid] = r4[tid] * expf(r3[tid] - nmb) + z2b * expf(m2b - nmb);
            r3[tid] = nmb;
        }
        __syncthreads();
    }
    if (tid == 0) {
        float* q = &g_part[(r * PARTS + part) * 5];
        q[0] = r0[0]; q[1] = r1[0]; q[2] = r2[0]; q[3] = r3[0]; q[4] = r4[0];
    }
}

__global__ void k_final(float* __restrict__ out) {
    __shared__ float acc[128];
    int r = threadIdx.x;
    float term = 0.0f;
    if (r < ROWS) {
        float mt = -INFINITY, zt = 0.f, st = 0.f, ms = -INFINITY, zs = 0.f;
        for (int p = 0; p < PARTS; p++) {
            const float* q = &g_part[(r * PARTS + p) * 5];
            float m2 = q[0], z2 = q[1], s2 = q[2];
            float nm = fmaxf(mt, m2);
            float e1 = expf(mt - nm), e2 = expf(m2 - nm);
            zt = zt * e1 + z2 * e2;
            st = st * e1 + s2 * e2;
            mt = nm;
            float m2b = q[3], z2b = q[4];
            float nmb = fmaxf(ms, m2b);
            zs = zs * expf(ms - nmb) + z2b * expf(m2b - nmb);
            ms = nmb;
        }
        term = st / zt - (mt + logf(zt)) + (ms + logf(zs));
    }
    acc[threadIdx.x] = term;
    __syncthreads();
    for (int off = 64; off > 0; off >>= 1) {
        if (threadIdx.x < off) acc[threadIdx.x] += acc[threadIdx.x + off];
        __syncthreads();
    }
    if (threadIdx.x == 0) out[0] = acc[0] / 112.0f;
}

// ---------------- launch ----------------
extern "C" void kernel_launch(void* const* d_in, const int* in_sizes, int n_in,
                              void* d_out, int out_size) {
    const float* S = (const float*)d_in[0];
    const float* T = (const float*)d_in[1];
    float* out = (float*)d_out;
    const int thr = 256;
    const int blks = PIX / thr;

    k_argmax<<<PIX / 4 / thr, thr>>>(T);
    k_sobel<<<blks, thr>>>();
    k_nms<<<blks, thr>>>();
    k_hyst_dil<<<Nn * 16, 256>>>();
    k_blur_h<<<(PIX / 32 + thr - 1) / thr, thr>>>();
    k_blur_v<<<blks, thr>>>();
    dim3 g(ROWS, PARTS);
    k_kd<<<g, 256>>>(S, T);
    k_final<<<1, 128>>>(out);
}

// round 3
// speedup vs baseline: 2.2994x; 1.1632x over previous
#include <cuda_runtime.h>
#include <math.h>

#define Nn 8
#define Cc 14
#define Hh 512
#define Ww 512
#define HW (Hh*Ww)
#define PIX (Nn*HW)
#define ROWS (Nn*Cc)   // 112
#define PARTS 8
#define WPR 16         // 512-bit row = 16 u32 words

// ---- scratch ----
__device__ unsigned char  g_tmap[PIX];
__device__ unsigned int   g_strongb[PIX/32];
__device__ unsigned int   g_weakb[PIX/32];
__device__ unsigned int   g_dvb[PIX/32];
__device__ float          g_e[PIX];
__device__ float          g_part[ROWS*PARTS*3];

// ---------------- 1. teacher argmax -> uint8 gray map (8 px/thread) ----------------
__global__ void k_argmax(const float* __restrict__ T) {
    int p8 = blockIdx.x * blockDim.x + threadIdx.x;
    if (p8 >= PIX / 8) return;
    int n = p8 / (HW / 8), sp8 = p8 % (HW / 8);
    const float4* base = (const float4*)(T + (size_t)n * Cc * HW) + sp8 * 2;
    float best[8]; int id[8];
    {
        float4 a = base[0], b = base[1];
        best[0]=a.x; best[1]=a.y; best[2]=a.z; best[3]=a.w;
        best[4]=b.x; best[5]=b.y; best[6]=b.z; best[7]=b.w;
#pragma unroll
        for (int j = 0; j < 8; j++) id[j] = 0;
    }
#pragma unroll
    for (int c = 1; c < Cc; c++) {
        float4 a = base[(size_t)c * (HW / 4)];
        float4 b = base[(size_t)c * (HW / 4) + 1];
        float v[8] = {a.x,a.y,a.z,a.w,b.x,b.y,b.z,b.w};
#pragma unroll
        for (int j = 0; j < 8; j++)
            if (v[j] > best[j]) { best[j] = v[j]; id[j] = c; }
    }
    unsigned lo = 0, hi = 0;
#pragma unroll
    for (int j = 0; j < 4; j++) {
        lo |= (unsigned)((unsigned char)((float)id[j]     / 13.0f * 255.0f)) << (8*j);
        hi |= (unsigned)((unsigned char)((float)id[j + 4] / 13.0f * 255.0f)) << (8*j);
    }
    ((uint2*)g_tmap)[p8] = make_uint2(lo, hi);
}

// ---------------- 2. fused Sobel + NMS -> bit-packed strong/weak ----------------
__global__ void k_sobel_nms() {
    __shared__ unsigned char tm[36*36];
    __shared__ unsigned short msec[34*34];   // mag<<2 | sect (mag <= 2040 fits 12 bits)
    int img = blockIdx.x >> 8;
    int t   = blockIdx.x & 255;
    int ty0 = (t >> 4) * 32, tx0 = (t & 15) * 32;
    int tid = threadIdx.x;
    const unsigned char* base = g_tmap + img * HW;
    for (int i = tid; i < 36*36; i += 256) {
        int ly = i / 36, lx = i % 36;
        int gy = ty0 + ly - 2; gy = gy < 0 ? 0 : (gy > 511 ? 511 : gy);
        int gx = tx0 + lx - 2; gx = gx < 0 ? 0 : (gx > 511 ? 511 : gx);
        tm[i] = base[gy * Ww + gx];
    }
    __syncthreads();
    for (int i = tid; i < 34*34; i += 256) {
        int ly = i / 34, lx = i % 34;
        const unsigned char* q = tm + ly * 36 + lx;
        int a0=q[0], a1=q[1], a2=q[2];
        int a3=q[36],          a5=q[38];
        int a6=q[72], a7=q[73], a8=q[74];
        int gx = (a2 + 2*a5 + a8) - (a0 + 2*a3 + a6);
        int gy = (a6 + 2*a7 + a8) - (a0 + 2*a1 + a2);
        int mag = abs(gx) + abs(gy);
        float ang = atan2f((float)gy, (float)gx) * 57.29577951308232f;
        if (ang < 0.0f)    ang += 180.0f;
        if (ang >= 180.0f) ang -= 180.0f;
        int s;
        if (ang < 22.5f || ang >= 157.5f) s = 0;
        else if (ang < 67.5f)             s = 1;
        else if (ang < 112.5f)            s = 2;
        else                              s = 3;
        msec[i] = (unsigned short)((mag << 2) | s);
    }
    __syncthreads();
#pragma unroll
    for (int k = 0; k < 4; k++) {
        int p = k * 256 + tid;            // 0..1023 core px
        int ly = p >> 5, lx = p & 31;
        int gy = ty0 + ly, gx = tx0 + lx;
        int v = msec[(ly+1)*34 + (lx+1)];
        int m = v >> 2, s = v & 3;
        int dy1, dx1, dy2, dx2;
        if (s == 0)      { dy1 = 0;  dx1 = 1;  dy2 = 0; dx2 = -1; }
        else if (s == 1) { dy1 = -1; dx1 = 1;  dy2 = 1; dx2 = -1; }
        else if (s == 2) { dy1 = -1; dx1 = 0;  dy2 = 1; dx2 = 0;  }
        else             { dy1 = -1; dx1 = -1; dy2 = 1; dx2 = 1;  }
        int y1 = gy + dy1, x1 = gx + dx1, y2 = gy + dy2, x2 = gx + dx2;
        int n1 = (y1 < 0 || y1 >= Hh || x1 < 0 || x1 >= Ww) ? 0
               : (msec[(ly+1+dy1)*34 + (lx+1+dx1)] >> 2);
        int n2 = (y2 < 0 || y2 >= Hh || x2 < 0 || x2 >= Ww) ? 0
               : (msec[(ly+1+dy2)*34 + (lx+1+dx2)] >> 2);
        int nms = (m >= n1 && m >= n2) ? m : 0;
        unsigned sm = __ballot_sync(0xffffffffu, nms > 50);
        unsigned wm = __ballot_sync(0xffffffffu, nms > 10);
        if (lx == 0) {
            int w = (img * Hh + gy) * WPR + (tx0 >> 5);
            g_strongb[w] = sm;
            g_weakb[w]   = wm;
        }
    }
}

// ---------------- 3. bitboard hysteresis (16 it) + fused 10x10 dilate, 64x64 tiles ----------------
#define TW 448   // 112 rows x 4 words
__global__ void k_hyst_dil() {
    __shared__ unsigned wk[TW], A[TW], B[TW];
    int img = blockIdx.x >> 6;
    int t   = blockIdx.x & 63;
    int ty = t >> 3, tx = t & 7;
    int gy0 = ty * 64 - 24;
    int gw0 = tx * 2 - 1;
    int tid = threadIdx.x;
    for (int i = tid; i < TW; i += 224) {
        int row = i >> 2, wi = i & 3;
        int gy = gy0 + row, gw = gw0 + wi;
        bool in = (gy >= 0 && gy < Hh && gw >= 0 && gw < WPR);
        int idx = (img * Hh + gy) * WPR + gw;
        wk[i] = in ? g_weakb[idx]   : 0u;
        A[i]  = in ? g_strongb[idx] : 0u;
    }
    __syncthreads();
    unsigned* cur = A;
    unsigned* nxt = B;
    for (int it = 0; it < 16; it++) {
        for (int i = tid; i < TW; i += 224) {
            int row = i >> 2, wi = i & 3;
            unsigned out = 0;
#pragma unroll
            for (int dr = -1; dr <= 1; dr++) {
                int rr = row + dr;
                if (rr >= 0 && rr < 112) {
                    unsigned c = cur[rr*4 + wi];
                    unsigned l = wi       ? cur[rr*4 + wi - 1] : 0u;
                    unsigned r = (wi < 3) ? cur[rr*4 + wi + 1] : 0u;
                    out |= c | (c << 1) | (l >> 31) | (c >> 1) | (r << 31);
                }
            }
            nxt[i] = wk[i] & out;
        }
        __syncthreads();
        unsigned* tmp = cur; cur = nxt; nxt = tmp;
    }
    // horizontal dilate [x-5, x+4] -> nxt
    for (int i = tid; i < TW; i += 224) {
        int wi = i & 3;
        unsigned c = cur[i];
        unsigned l = wi       ? cur[i - 1] : 0u;
        unsigned r = (wi < 3) ? cur[i + 1] : 0u;
        unsigned long long lo = (unsigned long long)l | ((unsigned long long)c << 32);
        unsigned long long hi = (unsigned long long)c | ((unsigned long long)r << 32);
        unsigned o = 0;
#pragma unroll
        for (int d = 0; d <= 4; d++) o |= (unsigned)(hi >> d);
#pragma unroll
        for (int d = 1; d <= 5; d++) o |= (unsigned)(lo >> (32 - d));
        nxt[i] = o;
    }
    __syncthreads();
    // vertical dilate [y-5, y+4]; core rows [24,88), core words wi in {1,2}
    for (int i = tid; i < 128; i += 224) {
        int row = (i >> 1) + 24, wi = (i & 1) + 1;
        unsigned o = 0;
#pragma unroll
        for (int dy = -5; dy <= 4; dy++) o |= nxt[(row + dy)*4 + wi];
        int gy = gy0 + row, gw = gw0 + wi;
        g_dvb[(img * Hh + gy) * WPR + gw] = o;
    }
}

// ---------------- 4. fused blur (h popcount -> SMEM bytes, v packed add) ----------------
__global__ void k_blur() {
    __shared__ unsigned char sh[41 * 512];   // bh rows [r0-5, r0+35] as bytes
    int img = blockIdx.x >> 4;
    int strip = blockIdx.x & 15;
    int r0 = strip * 32;
    int tid = threadIdx.x;
    // step 1: horizontal 10-window popcounts for 41 rows
    for (int i = tid; i < 41 * WPR; i += 256) {
        int rr = i >> 4, wi = i & 15;
        int y = r0 - 5 + rr; y = y < 0 ? 0 : (y > 511 ? 511 : y);
        int base = (img * Hh + y) * WPR;
        unsigned wc = g_dvb[base + wi];
        unsigned wl = wi        ? g_dvb[base + wi - 1] : 0u;
        unsigned wr = (wi < 15) ? g_dvb[base + wi + 1] : 0u;
        unsigned long long lo = (unsigned long long)wl | ((unsigned long long)wc << 32);
        unsigned long long hi = (unsigned long long)wc | ((unsigned long long)wr << 32);
        unsigned packs[8] = {0,0,0,0,0,0,0,0};
#pragma unroll
        for (int b = 0; b < 32; b++) {
            int x = wi * 32 + b;
            int s;
            if (x >= 5 && x < Ww - 4) {
                unsigned long long win = (b <= 27) ? (lo >> (b + 27)) : (hi >> (b - 5));
                s = __popcll(win & 0x3FFull);
            } else {
                s = 0;
                for (int dx = -5; dx <= 4; dx++) {
                    int xx = x + dx;
                    if (xx < 0) xx = -xx;
                    else if (xx >= Ww) xx = 2 * Ww - 2 - xx;
                    s += (wc >> (xx - wi * 32)) & 1;
                }
            }
            packs[b >> 2] |= (unsigned)s << ((b & 3) * 8);
        }
        unsigned* dst = (unsigned*)sh + rr * 128 + wi * 8;
#pragma unroll
        for (int q = 0; q < 8; q++) dst[q] = packs[q];
    }
    __syncthreads();
    // step 2: vertical sum of packed bytes (max 100/byte, no carry), round, /255
    for (int i = tid; i < 32 * 128; i += 256) {
        int ly = i >> 7, xc = i & 127;
        int y = r0 + ly;
        unsigned acc = 0;
#pragma unroll
        for (int dy = -5; dy <= 4; dy++) {
            int yy = y + dy;
            if (yy < 0) yy = -yy;
            else if (yy >= Hh) yy = 2 * Hh - 2 - yy;
            acc += ((unsigned*)sh)[(yy - (r0 - 5)) * 128 + xc];
        }
        float4 o;
        o.x = rintf((float)(((acc      ) & 255u) * 255u) / 100.0f) / 255.0f;
        o.y = rintf((float)(((acc >> 8 ) & 255u) * 255u) / 100.0f) / 255.0f;
        o.z = rintf((float)(((acc >> 16) & 255u) * 255u) / 100.0f) / 255.0f;
        o.w = rintf((float)(((acc >> 24) & 255u) * 255u) / 100.0f) / 255.0f;
        ((float4*)(g_e + (size_t)img * HW + y * Ww))[xc] = o;
    }
}

// ---------------- 5. masked channel-softmax KL (no-shift, __expf) ----------------
__global__ void k_kd(const float* __restrict__ S, const float* __restrict__ T) {
    int r = blockIdx.x;                 // (n,c)
    int part = blockIdx.y;
    int n = r / Cc, c = r % Cc;
    const float4* e4 = (const float4*)(g_e + (size_t)n * HW);
    const float4* t4 = (const float4*)(T + ((size_t)n * Cc + c) * HW);
    const float4* s4 = (const float4*)(S + ((size_t)n * Cc + c) * HW);
    const int q4 = HW / 4 / PARTS;
    const int base = part * q4;

    float zt = 0.f, st = 0.f, zs = 0.f;
    for (int k = threadIdx.x; k < q4; k += blockDim.x) {
        float4 ev = e4[base + k];
        if (ev.x + ev.y + ev.z + ev.w == 0.0f) { zt += 4.0f; zs += 4.0f; continue; }
        float4 tv = t4[base + k];
        float4 sv = s4[base + k];
        float el[4] = {ev.x, ev.y, ev.z, ev.w};
        float tl[4] = {tv.x, tv.y, tv.z, tv.w};
        float sl[4] = {sv.x, sv.y, sv.z, sv.w};
#pragma unroll
        for (int j = 0; j < 4; j++) {
            float xt = el[j] * tl[j];
            float xs = el[j] * sl[j];
            float et = __expf(xt);
            zt += et;
            zs += __expf(xs);
            st += et * (xt - xs);
        }
    }
    __shared__ float r1[256], r2[256], r3[256];
    int tid = threadIdx.x;
    r1[tid] = zt; r2[tid] = st; r3[tid] = zs;
    __syncthreads();
    for (int off = 128; off > 0; off >>= 1) {
        if (tid < off) {
            r1[tid] += r1[tid + off];
            r2[tid] += r2[tid + off];
            r3[tid] += r3[tid + off];
        }
        __syncthreads();
    }
    if (tid == 0) {
        float* q = &g_part[(r * PARTS + part) * 3];
        q[0] = r1[0]; q[1] = r2[0]; q[2] = r3[0];
    }
}

__global__ void k_final(float* __restrict__ out) {
    __shared__ float acc[128];
    int r = threadIdx.x;
    float term = 0.0f;
    if (r < ROWS) {
        float zt = 0.f, st = 0.f, zs = 0.f;
        for (int p = 0; p < PARTS; p++) {
            const float* q = &g_part[(r * PARTS + p) * 3];
            zt += q[0]; st += q[1]; zs += q[2];
        }
        term = st / zt - logf(zt) + logf(zs);
    }
    acc[threadIdx.x] = term;
    __syncthreads();
    for (int off = 64; off > 0; off >>= 1) {
        if (threadIdx.x < off) acc[threadIdx.x] += acc[threadIdx.x + off];
        __syncthreads();
    }
    if (threadIdx.x == 0) out[0] = acc[0] / 112.0f;
}

// ---------------- launch ----------------
extern "C" void kernel_launch(void* const* d_in, const int* in_sizes, int n_in,
                              void* d_out, int out_size) {
    const float* S = (const float*)d_in[0];
    const float* T = (const float*)d_in[1];
    float* out = (float*)d_out;

    k_argmax<<<PIX / 8 / 256, 256>>>(T);
    k_sobel_nms<<<Nn * 256, 256>>>();
    k_hyst_dil<<<Nn * 64, 224>>>();
    k_blur<<<Nn * 16, 256>>>();
    dim3 g(ROWS, PARTS);
    k_kd<<<g, 256>>>(S, T);
    k_final<<<1, 128>>>(out);
}

// round 4
// speedup vs baseline: 2.3929x; 1.0407x over previous
#include <cuda_runtime.h>
#include <math.h>

#define Nn 8
#define Cc 14
#define Hh 512
#define Ww 512
#define HW (Hh*Ww)
#define PIX (Nn*HW)
#define ROWS (Nn*Cc)   // 112
#define PARTS 8
#define WPR 16         // 512-bit row = 16 u32 words

// ---- scratch ----
__device__ unsigned char  g_tmap[PIX];
__device__ unsigned int   g_strongb[PIX/32];
__device__ unsigned int   g_weakb[PIX/32];
__device__ float          g_e[PIX];
__device__ float          g_part[ROWS*PARTS*3];

// ---------------- 1. teacher argmax -> uint8 gray map (8 px/thread) ----------------
__global__ void k_argmax(const float* __restrict__ T) {
    int p8 = blockIdx.x * blockDim.x + threadIdx.x;
    if (p8 >= PIX / 8) return;
    int n = p8 / (HW / 8), sp8 = p8 % (HW / 8);
    const float4* base = (const float4*)(T + (size_t)n * Cc * HW) + sp8 * 2;
    float best[8]; int id[8];
    {
        float4 a = base[0], b = base[1];
        best[0]=a.x; best[1]=a.y; best[2]=a.z; best[3]=a.w;
        best[4]=b.x; best[5]=b.y; best[6]=b.z; best[7]=b.w;
#pragma unroll
        for (int j = 0; j < 8; j++) id[j] = 0;
    }
#pragma unroll
    for (int c = 1; c < Cc; c++) {
        float4 a = base[(size_t)c * (HW / 4)];
        float4 b = base[(size_t)c * (HW / 4) + 1];
        float v[8] = {a.x,a.y,a.z,a.w,b.x,b.y,b.z,b.w};
#pragma unroll
        for (int j = 0; j < 8; j++)
            if (v[j] > best[j]) { best[j] = v[j]; id[j] = c; }
    }
    unsigned lo = 0, hi = 0;
#pragma unroll
    for (int j = 0; j < 4; j++) {
        lo |= (unsigned)((unsigned char)((float)id[j]     / 13.0f * 255.0f)) << (8*j);
        hi |= (unsigned)((unsigned char)((float)id[j + 4] / 13.0f * 255.0f)) << (8*j);
    }
    ((uint2*)g_tmap)[p8] = make_uint2(lo, hi);
}

// ---------------- 2. fused Sobel + NMS (branch-free sectors) ----------------
__global__ void k_sobel_nms() {
    __shared__ unsigned char tm[36*36];
    __shared__ unsigned short msec[34*34];   // mag<<2 | sect
    int img = blockIdx.x >> 8;
    int t   = blockIdx.x & 255;
    int ty0 = (t >> 4) * 32, tx0 = (t & 15) * 32;
    int tid = threadIdx.x;
    const unsigned char* base = g_tmap + img * HW;
    for (int i = tid; i < 36*36; i += 256) {
        int ly = i / 36, lx = i % 36;
        int gy = ty0 + ly - 2; gy = gy < 0 ? 0 : (gy > 511 ? 511 : gy);
        int gx = tx0 + lx - 2; gx = gx < 0 ? 0 : (gx > 511 ? 511 : gx);
        tm[i] = base[gy * Ww + gx];
    }
    __syncthreads();
    for (int i = tid; i < 34*34; i += 256) {
        int ly = i / 34, lx = i % 34;
        const unsigned char* q = tm + ly * 36 + lx;
        int a0=q[0], a1=q[1], a2=q[2];
        int a3=q[36],          a5=q[38];
        int a6=q[72], a7=q[73], a8=q[74];
        int gx = (a2 + 2*a5 + a8) - (a0 + 2*a3 + a6);
        int gy = (a6 + 2*a7 + a8) - (a0 + 2*a1 + a2);
        int mag = abs(gx) + abs(gy);
        // sector via tan thresholds (atan2-free); ang = atan2(gy,gx) mod 180
        float fax = (float)abs(gx), fay = (float)abs(gy);
        int s;
        if (fay < 0.41421356f * fax)      s = 0;
        else if (fay < 2.41421356f * fax) s = ((gx ^ gy) >= 0) ? 1 : 3;
        else                              s = 2;
        msec[i] = (unsigned short)((mag << 2) | s);
    }
    __syncthreads();
#pragma unroll
    for (int k = 0; k < 4; k++) {
        int p = k * 256 + tid;            // 0..1023 core px
        int ly = p >> 5, lx = p & 31;
        int gy = ty0 + ly, gx = tx0 + lx;
        int v = msec[(ly+1)*34 + (lx+1)];
        int m = v >> 2, s = v & 3;
        int dy1, dx1, dy2, dx2;
        if (s == 0)      { dy1 = 0;  dx1 = 1;  dy2 = 0; dx2 = -1; }
        else if (s == 1) { dy1 = -1; dx1 = 1;  dy2 = 1; dx2 = -1; }
        else if (s == 2) { dy1 = -1; dx1 = 0;  dy2 = 1; dx2 = 0;  }
        else             { dy1 = -1; dx1 = -1; dy2 = 1; dx2 = 1;  }
        int y1 = gy + dy1, x1 = gx + dx1, y2 = gy + dy2, x2 = gx + dx2;
        int n1 = (y1 < 0 || y1 >= Hh || x1 < 0 || x1 >= Ww) ? 0
               : (msec[(ly+1+dy1)*34 + (lx+1+dx1)] >> 2);
        int n2 = (y2 < 0 || y2 >= Hh || x2 < 0 || x2 >= Ww) ? 0
               : (msec[(ly+1+dy2)*34 + (lx+1+dx2)] >> 2);
        int nms = (m >= n1 && m >= n2) ? m : 0;
        unsigned sm = __ballot_sync(0xffffffffu, nms > 50);
        unsigned wm = __ballot_sync(0xffffffffu, nms > 10);
        if (lx == 0) {
            int w = (img * Hh + gy) * WPR + (tx0 >> 5);
            g_strongb[w] = sm;
            g_weakb[w]   = wm;
        }
    }
}

// ---------------- 3. hysteresis(16) + dilate 10x10 + blur 10x10, one kernel ----------------
// 64x64 core tiles; halo 26 = 16 (hyst) + 5 (dilate) + 5 (blur). Rows 116 x 4 words.
#define TROWS 116
#define TW (TROWS*4)   // 464
__global__ void k_edge() {
    __shared__ unsigned wk[TW], A[TW], B[TW];
    __shared__ unsigned shp[74*16];          // h-blur popcounts as packed bytes
    int img = blockIdx.x >> 6;
    int t   = blockIdx.x & 63;
    int ty = t >> 3, tx = t & 7;
    int y0  = ty * 64;
    int x0  = tx * 64;
    int gy0 = y0 - 26;
    int gw0 = tx * 2 - 1;
    int tid = threadIdx.x;
    for (int i = tid; i < TW; i += 256) {
        int row = i >> 2, wi = i & 3;
        int gy = gy0 + row, gw = gw0 + wi;
        bool in = (gy >= 0 && gy < Hh && gw >= 0 && gw < WPR);
        int idx = (img * Hh + gy) * WPR + gw;
        wk[i] = in ? g_weakb[idx]   : 0u;
        A[i]  = in ? g_strongb[idx] : 0u;
    }
    __syncthreads();
    unsigned* cur = A;
    unsigned* nxt = B;
    for (int it = 0; it < 16; it++) {
        for (int i = tid; i < TW; i += 256) {
            int row = i >> 2, wi = i & 3;
            unsigned out = 0;
#pragma unroll
            for (int dr = -1; dr <= 1; dr++) {
                int rr = row + dr;
                if ((unsigned)rr < TROWS) {
                    int b2 = rr * 4 + wi;
                    unsigned c = cur[b2];
                    unsigned l = wi       ? cur[b2 - 1] : 0u;
                    unsigned r = (wi < 3) ? cur[b2 + 1] : 0u;
                    out |= c | (c << 1) | (l >> 31) | (c >> 1) | (r << 31);
                }
            }
            nxt[i] = wk[i] & out;
        }
        __syncthreads();
        unsigned* tmp = cur; cur = nxt; nxt = tmp;
    }
    // horizontal dilate [x-5,x+4] -> nxt
    for (int i = tid; i < TW; i += 256) {
        int wi = i & 3;
        unsigned c = cur[i];
        unsigned l = wi       ? cur[i - 1] : 0u;
        unsigned r = (wi < 3) ? cur[i + 1] : 0u;
        unsigned long long lo = (unsigned long long)l | ((unsigned long long)c << 32);
        unsigned long long hi = (unsigned long long)c | ((unsigned long long)r << 32);
        unsigned o = 0;
#pragma unroll
        for (int d = 0; d <= 4; d++) o |= (unsigned)(hi >> d);
#pragma unroll
        for (int d = 1; d <= 5; d++) o |= (unsigned)(lo >> (32 - d));
        nxt[i] = o;
    }
    __syncthreads();
    // vertical dilate [y-5,y+4] for tile rows 21..94 -> wk (reused as dv)
    for (int i = tid; i < 74 * 4; i += 256) {
        int rr = i >> 2, wi = i & 3;
        int row = 21 + rr;
        unsigned o = 0;
#pragma unroll
        for (int dy = -5; dy <= 4; dy++) o |= nxt[(row + dy) * 4 + wi];
        wk[i] = o;
    }
    __syncthreads();
    // blur horizontal: 10-bit popcounts for 74 rows x 64 cols, reflect101 at image edge
    for (int i = tid; i < 74 * 16; i += 256) {
        int rr = i >> 4, g = i & 15;
        unsigned w0 = wk[rr*4], w1 = wk[rr*4+1], w2 = wk[rr*4+2], w3 = wk[rr*4+3];
        unsigned wv[4] = {w0, w1, w2, w3};
        unsigned pack = 0;
#pragma unroll
        for (int jj = 0; jj < 4; jj++) {
            int j = g * 4 + jj;
            int x = x0 + j;
            int s;
            if (x >= 5 && x <= Ww - 5) {
                int p = 27 + j;                       // window start bit
                int idx = p >> 5, off = p & 31;
                unsigned win = __funnelshift_r(wv[idx], wv[idx + 1 < 4 ? idx + 1 : 3], off);
                s = __popc(win & 0x3FFu);
            } else {
                s = 0;
                for (int dx = -5; dx <= 4; dx++) {
                    int xx = x + dx;
                    if (xx < 0) xx = -xx;
                    else if (xx >= Ww) xx = 2 * Ww - 2 - xx;
                    int bit = xx - x0 + 32;
                    s += (wv[bit >> 5] >> (bit & 31)) & 1;
                }
            }
            pack |= (unsigned)s << (8 * jj);
        }
        shp[i] = pack;
    }
    __syncthreads();
    // blur vertical: sum 10 packed-byte rows (max 100/byte), round, /255
    for (int i = tid; i < 64 * 16; i += 256) {
        int ly = i >> 4, g = i & 15;
        int y = y0 + ly;
        unsigned acc = 0;
#pragma unroll
        for (int dy = -5; dy <= 4; dy++) {
            int yy = y + dy;
            if (yy < 0) yy = -yy;
            else if (yy >= Hh) yy = 2 * Hh - 2 - yy;
            acc += shp[(yy - y0 + 5) * 16 + g];
        }
        float4 o;
        o.x = rintf((float)(((acc      ) & 255u) * 255u) / 100.0f) / 255.0f;
        o.y = rintf((float)(((acc >> 8 ) & 255u) * 255u) / 100.0f) / 255.0f;
        o.z = rintf((float)(((acc >> 16) & 255u) * 255u) / 100.0f) / 255.0f;
        o.w = rintf((float)(((acc >> 24) & 255u) * 255u) / 100.0f) / 255.0f;
        *(float4*)(g_e + (size_t)img * HW + y * Ww + x0 + g * 4) = o;
    }
}

// ---------------- 4. masked channel-softmax KL (no-shift, __expf) ----------------
__global__ void k_kd(const float* __restrict__ S, const float* __restrict__ T) {
    int r = blockIdx.x;                 // (n,c)
    int part = blockIdx.y;
    int n = r / Cc, c = r % Cc;
    const float4* e4 = (const float4*)(g_e + (size_t)n * HW);
    const float4* t4 = (const float4*)(T + ((size_t)n * Cc + c) * HW);
    const float4* s4 = (const float4*)(S + ((size_t)n * Cc + c) * HW);
    const int q4 = HW / 4 / PARTS;
    const int base = part * q4;

    float zt = 0.f, st = 0.f, zs = 0.f;
#pragma unroll 2
    for (int k = threadIdx.x; k < q4; k += blockDim.x) {
        float4 ev = e4[base + k];
        float4 tv = t4[base + k];
        float4 sv = s4[base + k];
        float el[4] = {ev.x, ev.y, ev.z, ev.w};
        float tl[4] = {tv.x, tv.y, tv.z, tv.w};
        float sl[4] = {sv.x, sv.y, sv.z, sv.w};
#pragma unroll
        for (int j = 0; j < 4; j++) {
            float xt = el[j] * tl[j];
            float xs = el[j] * sl[j];
            float et = __expf(xt);
            zt += et;
            zs += __expf(xs);
            st += et * (xt - xs);
        }
    }
    __shared__ float r1[256], r2[256], r3[256];
    int tid = threadIdx.x;
    r1[tid] = zt; r2[tid] = st; r3[tid] = zs;
    __syncthreads();
    for (int off = 128; off > 0; off >>= 1) {
        if (tid < off) {
            r1[tid] += r1[tid + off];
            r2[tid] += r2[tid + off];
            r3[tid] += r3[tid + off];
        }
        __syncthreads();
    }
    if (tid == 0) {
        float* q = &g_part[(r * PARTS + part) * 3];
        q[0] = r1[0]; q[1] = r2[0]; q[2] = r3[0];
    }
}

__global__ void k_final(float* __restrict__ out) {
    __shared__ float acc[128];
    int r = threadIdx.x;
    float term = 0.0f;
    if (r < ROWS) {
        float zt = 0.f, st = 0.f, zs = 0.f;
        for (int p = 0; p < PARTS; p++) {
            const float* q = &g_part[(r * PARTS + p) * 3];
            zt += q[0]; st += q[1]; zs += q[2];
        }
        term = st / zt - logf(zt) + logf(zs);
    }
    acc[threadIdx.x] = term;
    __syncthreads();
    for (int off = 64; off > 0; off >>= 1) {
        if (threadIdx.x < off) acc[threadIdx.x] += acc[threadIdx.x + off];
        __syncthreads();
    }
    if (threadIdx.x == 0) out[0] = acc[0] / 112.0f;
}

// ---------------- launch ----------------
extern "C" void kernel_launch(void* const* d_in, const int* in_sizes, int n_in,
                              void* d_out, int out_size) {
    const float* S = (const float*)d_in[0];
    const float* T = (const float*)d_in[1];
    float* out = (float*)d_out;

    k_argmax<<<PIX / 8 / 256, 256>>>(T);
    k_sobel_nms<<<Nn * 256, 256>>>();
    k_edge<<<Nn * 64, 256>>>();
    dim3 g(ROWS, PARTS);
    k_kd<<<g, 256>>>(S, T);
    k_final<<<1, 128>>>(out);
}